// round 5
// baseline (speedup 1.0000x reference)
#include <cuda_runtime.h>
#include <math.h>

// ---------------------------------------------------------------------------
// corr[u] = Sum_t x1[t] * Re(U[(t-u) mod h]),  U = separable Dirichlet
// upsample of the coarser x2.  For h = r*m, phi(t)=0 when t%r==0 (t!=0),
// phi(0)=1 -> outputs t%r==0 are copies; others use compacted residue tables
// phi_c[d] = phi(r*d+c).  phi(t) = (1/m) e^{-i pi t/h} sin(pi t m/h)/sin(pi t/h)
//   re = cospi(a)*sinpi(m a)/(m sinpi(a)),  im = -sinpi(m a)/m,  a = t/h.
// All arguments are exact binary fractions -> sinpif reduction exact.
// 4 launches: memset | K1 = upA(all) + same-scale corr | K2 = upB(all) |
// K3 = cross-scale corr.
// Output [2, 6*64, 7]; shifts (0,0),(0,1),(0,2),(1,0),(1,1),(2,0),(-1,1).
// ---------------------------------------------------------------------------

#define LCH 8

__device__ float2 g_A01[16 * 128 * 256]; // y-upsampled (complex)
__device__ float2 g_A02[16 * 64 * 256];
__device__ float2 g_A12[16 * 64 * 128];
__device__ float  g_U01[16 * 256 * 256]; // fully upsampled (real)
__device__ float  g_U02[16 * 256 * 256];
__device__ float  g_U12[16 * 128 * 128];

__constant__ int c_dx[7] = {0, 0, 0, 1, 1, 2, -1};
__constant__ int c_dy[7] = {0, 1, 2, 0, 1, 0, 1};

__device__ __forceinline__ float2 phi_val(int t, int m, float inv_h) {
    float a  = (float)t * inv_h;              // exact
    float sm = sinpif((float)m * a);          // exact reduction (m*a = k/2 or k/4)
    float sd = sinpif(a);
    float s  = sm / (sd * (float)m);
    return make_float2(cospif(a) * s, -sm / (float)m);
}

// ---- upA (y-direction upsample), r=2: 16 rows per block, 256 threads ----
template <int MM, int RS>
__device__ __forceinline__ void upA_r2_body(int blk, const float* __restrict__ x,
                                            float2* __restrict__ A, float* smraw) {
    const int HH = 2 * MM;
    const int RTOT = 16;
    float*  xs = smraw;                       // RTOT*MM floats
    float2* ps = (float2*)(smraw + RTOT * MM);
    int tid = threadIdx.x;
    if (tid < MM) ps[tid] = phi_val(2 * tid + 1, MM, 1.f / (float)HH);
    int row0 = blk * RTOT;
    const float* xb = x + (size_t)row0 * MM;
#pragma unroll
    for (int i = tid; i < RTOT * MM; i += 256) xs[i] = xb[i];
    __syncthreads();
    int g = tid / MM, u = tid & (MM - 1);
    float ar[RS], ai[RS];
#pragma unroll
    for (int rr = 0; rr < RS; ++rr) { ar[rr] = 0.f; ai[rr] = 0.f; }
    for (int qy = 0; qy < MM; qy += 4) {
        float2 p0 = ps[(u - qy)     & (MM - 1)];
        float2 p1 = ps[(u - qy - 1) & (MM - 1)];
        float2 p2 = ps[(u - qy - 2) & (MM - 1)];
        float2 p3 = ps[(u - qy - 3) & (MM - 1)];
#pragma unroll
        for (int rr = 0; rr < RS; ++rr) {
            float4 v = *(const float4*)&xs[(g * RS + rr) * MM + qy]; // broadcast
            ar[rr] += v.x * p0.x + v.y * p1.x + v.z * p2.x + v.w * p3.x;
            ai[rr] += v.x * p0.y + v.y * p1.y + v.z * p2.y + v.w * p3.y;
        }
    }
    float2* Ab = A + (size_t)row0 * HH;
#pragma unroll
    for (int rr = 0; rr < RS; ++rr) {
        int rloc = g * RS + rr;
        Ab[(size_t)rloc * HH + 2 * u + 1] = make_float2(ar[rr], ai[rr]);
        Ab[(size_t)rloc * HH + 2 * u]     = make_float2(xs[rloc * MM + u], 0.f);
    }
}

// ---- upA, r=4 (combo 02): 8 rows per block; tids 192-255 write copies ----
__device__ __forceinline__ void upA4_body(int blk, const float* __restrict__ x,
                                          float2* __restrict__ A, float* smraw) {
    float*  xs = smraw;                       // 8*64
    float2* ps = (float2*)(smraw + 512);      // 192 entries
    int tid = threadIdx.x;
    if (tid < 192) {
        int cls = tid >> 6, d = tid & 63;
        ps[tid] = phi_val(4 * d + cls + 1, 64, 1.f / 256.f);
    }
    int row0 = blk * 8;
    const float* xb = x + (size_t)row0 * 64;
    for (int i = tid; i < 512; i += 256) xs[i] = xb[i];
    __syncthreads();
    float2* Ab = A + (size_t)row0 * 256;
    if (tid < 192) {
        int cls = tid >> 6, u = tid & 63;
        const float2* pc = ps + cls * 64;
        float ar[8], ai[8];
#pragma unroll
        for (int rr = 0; rr < 8; ++rr) { ar[rr] = 0.f; ai[rr] = 0.f; }
        for (int qy = 0; qy < 64; qy += 4) {
            float2 p0 = pc[(u - qy)     & 63];
            float2 p1 = pc[(u - qy - 1) & 63];
            float2 p2 = pc[(u - qy - 2) & 63];
            float2 p3 = pc[(u - qy - 3) & 63];
#pragma unroll
            for (int rr = 0; rr < 8; ++rr) {
                float4 v = *(const float4*)&xs[rr * 64 + qy];
                ar[rr] += v.x * p0.x + v.y * p1.x + v.z * p2.x + v.w * p3.x;
                ai[rr] += v.x * p0.y + v.y * p1.y + v.z * p2.y + v.w * p3.y;
            }
        }
        int ty = 4 * u + cls + 1;
#pragma unroll
        for (int rr = 0; rr < 8; ++rr)
            Ab[(size_t)rr * 256 + ty] = make_float2(ar[rr], ai[rr]);
    } else {
        int u = tid - 192;
#pragma unroll
        for (int rr = 0; rr < 8; ++rr)
            Ab[(size_t)rr * 256 + 4 * u] = make_float2(xs[rr * 64 + u], 0.f);
    }
}

// ---- correlation body (8x8 Gram block at one shift over a 4096-q chunk) ----
__device__ __forceinline__ void corr_body(const float* __restrict__ A,
                                          const float* __restrict__ B,
                                          float* __restrict__ out,
                                          int lm, int qblk, int s, int b,
                                          int sg, int trans, int pbase,
                                          float* smraw) {
    int h = 1 << lm, hh = h * h;
    int dx = sg * c_dx[s], dy = sg * c_dy[s];
    const float* Ab = A + (size_t)b * LCH * hh;
    const float* Bb = B + (size_t)b * LCH * hh;
    int q0 = qblk * 4096;
    float acc[64];
#pragma unroll
    for (int k = 0; k < 64; ++k) acc[k] = 0.f;
    for (int q = q0 + threadIdx.x; q < q0 + 4096; q += 256) {
        int qx = q >> lm;
        int qy = q & (h - 1);
        int fo = (((qx + dx) & (h - 1)) << lm) + ((qy + dy) & (h - 1));
        float a[8], c[8];
#pragma unroll
        for (int l = 0; l < 8; ++l) a[l] = Ab[(size_t)l * hh + fo];
#pragma unroll
        for (int l = 0; l < 8; ++l) c[l] = Bb[(size_t)l * hh + q];
#pragma unroll
        for (int i = 0; i < 8; ++i)
#pragma unroll
            for (int j = 0; j < 8; ++j)
                acc[i * 8 + j] = fmaf(a[i], c[j], acc[i * 8 + j]);
    }
    float* red = smraw;                       // 64*8 floats
    int lane = threadIdx.x & 31;
    int wid  = threadIdx.x >> 5;
#pragma unroll
    for (int k = 0; k < 64; ++k) {
        float v = acc[k];
        v += __shfl_down_sync(0xffffffffu, v, 16);
        v += __shfl_down_sync(0xffffffffu, v, 8);
        v += __shfl_down_sync(0xffffffffu, v, 4);
        v += __shfl_down_sync(0xffffffffu, v, 2);
        v += __shfl_down_sync(0xffffffffu, v, 1);
        if (lane == 0) red[k * 8 + wid] = v;
    }
    __syncthreads();
    if (threadIdx.x < 64) {
        float sum = 0.f;
#pragma unroll
        for (int w8 = 0; w8 < 8; ++w8) sum += red[threadIdx.x * 8 + w8];
        int k = threadIdx.x;
        int p = trans ? (((k & 7) << 3) | (k >> 3)) : k;
        atomicAdd(&out[(size_t)b * 2688 + (size_t)(pbase + p) * 7 + s], sum);
    }
}

// ---- K1: all upA + all same-scale correlations (614 blocks) ----
__global__ void __launch_bounds__(256, 2) k1_kernel(const float* __restrict__ x0,
                                                    const float* __restrict__ x1,
                                                    const float* __restrict__ x2,
                                                    float* __restrict__ out) {
    extern __shared__ float smraw[];
    int bx = blockIdx.x;
    if (bx < 128) { upA_r2_body<128, 8>(bx, x1, g_A01, smraw); return; }
    bx -= 128;
    if (bx < 128) { upA4_body(bx, x2, g_A02, smraw); return; }
    bx -= 128;
    if (bx < 64)  { upA_r2_body<64, 4>(bx, x2, g_A12, smraw); return; }
    bx -= 64;                                  // 0..293: same-scale corr
    int qa = bx / 14, rem = bx % 14, s = rem >> 1, b = rem & 1;
    if (qa < 16)      corr_body(x0, x0, out, 8, qa,      s, b, 1, 0, 0,   smraw);
    else if (qa < 20) corr_body(x1, x1, out, 7, qa - 16, s, b, 1, 0, 192, smraw);
    else              corr_body(x2, x2, out, 6, 0,       s, b, 1, 0, 320, smraw);
}

// ---- upB core (r=2): 8 odd output rows per block, copy rows folded in ----
template <int MM>
__device__ __forceinline__ void upB2_core(int img, int t0, int ty,
                                          const float2* __restrict__ A,
                                          float* __restrict__ U,
                                          const float2* ps) {
    const int HH = 2 * MM;
    float acc[8];
#pragma unroll
    for (int i = 0; i < 8; ++i) acc[i] = 0.f;
    const float2* Ab = A + (size_t)img * MM * HH + ty;
    float* Ub = U + (size_t)img * HH * HH;
#pragma unroll 2
    for (int qx = 0; qx < MM; ++qx) {
        float2 av = Ab[(size_t)qx * HH];
        if ((unsigned)(qx - t0) < 8u) Ub[(size_t)(2 * qx) * HH + ty] = av.x;
        float nay = -av.y;
        int k0 = (t0 - qx) & (MM - 1);
#pragma unroll
        for (int i = 0; i < 8; ++i) {
            float2 p = ps[k0 + i];             // broadcast
            acc[i] = fmaf(av.x, p.x, acc[i]);
            acc[i] = fmaf(nay,  p.y, acc[i]);
        }
    }
#pragma unroll
    for (int i = 0; i < 8; ++i)
        Ub[(size_t)(2 * (t0 + i) + 1) * HH + ty] = acc[i];
}

// ---- upB core (r=4, combo 02): one residue class per block ----
__device__ __forceinline__ void upB4_core(int img, int t0, int cls, int ty,
                                          const float2* __restrict__ A,
                                          float* __restrict__ U,
                                          const float2* ps) {
    float acc[8];
#pragma unroll
    for (int i = 0; i < 8; ++i) acc[i] = 0.f;
    const float2* Ab = A + (size_t)img * 64 * 256 + ty;
    float* Ub = U + (size_t)img * 256 * 256;
#pragma unroll 2
    for (int qx = 0; qx < 64; ++qx) {
        float2 av = Ab[(size_t)qx * 256];
        if (cls == 0 && (unsigned)(qx - t0) < 8u)
            Ub[(size_t)(4 * qx) * 256 + ty] = av.x;
        float nay = -av.y;
        int k0 = (t0 - qx) & 63;
#pragma unroll
        for (int i = 0; i < 8; ++i) {
            float2 p = ps[k0 + i];
            acc[i] = fmaf(av.x, p.x, acc[i]);
            acc[i] = fmaf(nay,  p.y, acc[i]);
        }
    }
#pragma unroll
    for (int i = 0; i < 8; ++i)
        Ub[(size_t)(4 * (t0 + i) + cls + 1) * 256 + ty] = acc[i];
}

// ---- K2: all upB (704 blocks) ----
__global__ void __launch_bounds__(256, 2) k2_kernel() {
    extern __shared__ float smraw[];
    float2* ps = (float2*)smraw;
    int bx = blockIdx.x, tid = threadIdx.x;
    if (bx < 256) {                            // upB01: MM=128
        int img = bx >> 4, t0 = (bx & 15) * 8;
        if (tid < 128) { float2 v = phi_val(2 * tid + 1, 128, 1.f / 256.f); ps[tid] = v; ps[tid + 128] = v; }
        __syncthreads();
        upB2_core<128>(img, t0, tid, g_A01, g_U01, ps);
        return;
    }
    bx -= 256;
    if (bx < 384) {                            // upB02
        int img = bx / 24, r = bx % 24, cls = r >> 3, t0 = (r & 7) * 8;
        if (tid < 64) { float2 v = phi_val(4 * tid + cls + 1, 64, 1.f / 256.f); ps[tid] = v; ps[tid + 64] = v; }
        __syncthreads();
        upB4_core(img, t0, cls, tid, g_A02, g_U02, ps);
        return;
    }
    bx -= 384;                                 // upB12: 2 images per block
    {
        int imgp = bx >> 3, t0 = (bx & 7) * 8;
        if (tid < 64) { float2 v = phi_val(2 * tid + 1, 64, 1.f / 128.f); ps[tid] = v; ps[tid + 64] = v; }
        __syncthreads();
        int img = imgp * 2 + (tid >> 7), ty = tid & 127;
        upB2_core<64>(img, t0, ty, g_A12, g_U12, ps);
    }
}

// ---- K3: cross-scale correlations (36 x 7 x 2 blocks) ----
__global__ void __launch_bounds__(256, 2) k3_kernel(const float* __restrict__ x0,
                                                    const float* __restrict__ x1,
                                                    float* __restrict__ out) {
    extern __shared__ float smraw[];
    int bx = blockIdx.x, s = blockIdx.y, b = blockIdx.z;
    if (bx < 16)      corr_body(g_U01, x0, out, 8, bx,      s, b, -1, 1, 64,  smraw);
    else if (bx < 32) corr_body(g_U02, x0, out, 8, bx - 16, s, b, -1, 1, 128, smraw);
    else              corr_body(g_U12, x1, out, 7, bx - 32, s, b, -1, 1, 256, smraw);
}

extern "C" void kernel_launch(void* const* d_in, const int* in_sizes, int n_in,
                              void* d_out, int out_size) {
    const float* x0 = nullptr;
    const float* x1 = nullptr;
    const float* x2 = nullptr;
    for (int i = 0; i < n_in; ++i) {
        if (in_sizes[i] == 2 * 8 * 256 * 256)      x0 = (const float*)d_in[i];
        else if (in_sizes[i] == 2 * 8 * 128 * 128) x1 = (const float*)d_in[i];
        else if (in_sizes[i] == 2 * 8 * 64 * 64)   x2 = (const float*)d_in[i];
    }
    float* out = (float*)d_out;

    cudaMemsetAsync(d_out, 0, (size_t)out_size * sizeof(float));
    k1_kernel<<<614, 256, 9216>>>(x0, x1, x2, out);   // upA + same-scale corr
    k2_kernel<<<704, 256, 2048>>>();                  // upB
    k3_kernel<<<dim3(36, 7, 2), 256, 2048>>>(x0, x1, out); // cross-scale corr
}

// round 6
// speedup vs baseline: 1.4577x; 1.4577x over previous
#include <cuda_runtime.h>
#include <math.h>

// ---------------------------------------------------------------------------
// corr[u] = Sum_t x1[t] * Re(U[(t-u) mod h]),  U = separable Dirichlet
// upsample of the coarser x2.  For h = r*m, phi(t)=0 when t%r==0 (t!=0),
// phi(0)=1 -> outputs t%r==0 are copies; others use compacted residue tables.
// phi(t) = (1/m) e^{-i pi t/h} sin(pi t m/h)/sin(pi t/h), exact via sinpif.
// f32x2 packed FMA (FFMA2) halves the issue stream in all hot loops.
// 4 launches: memset | upA | upB | corr(all 6 groups).
// Output [2, 6*64, 7]; shifts (0,0),(0,1),(0,2),(1,0),(1,1),(2,0),(-1,1).
// ---------------------------------------------------------------------------

#define LCH 8
typedef unsigned long long u64;

__device__ float2 g_A01[16 * 128 * 256]; // y-upsampled (complex)
__device__ float2 g_A02[16 * 64 * 256];
__device__ float2 g_A12[16 * 64 * 128];
__device__ float  g_U01[16 * 256 * 256]; // fully upsampled (real)
__device__ float  g_U02[16 * 256 * 256];
__device__ float  g_U12[16 * 128 * 128];

__constant__ int c_dx[7] = {0, 0, 0, 1, 1, 2, -1};
__constant__ int c_dy[7] = {0, 1, 2, 0, 1, 0, 1};

__device__ __forceinline__ u64 pack2(float lo, float hi) {
    u64 r; asm("mov.b64 %0, {%1, %2};" : "=l"(r) : "f"(lo), "f"(hi)); return r;
}
__device__ __forceinline__ void unpack2(u64 v, float& lo, float& hi) {
    asm("mov.b64 {%0, %1}, %2;" : "=f"(lo), "=f"(hi) : "l"(v));
}
__device__ __forceinline__ void fma2(u64& d, u64 a, u64 b) {
    asm("fma.rn.f32x2 %0, %1, %2, %3;" : "=l"(d) : "l"(a), "l"(b), "l"(d));
}
__device__ __forceinline__ u64 add2(u64 a, u64 b) {
    u64 r; asm("add.rn.f32x2 %0, %1, %2;" : "=l"(r) : "l"(a), "l"(b)); return r;
}

__device__ __forceinline__ float2 phi_val(int t, int m, float inv_h) {
    float a  = (float)t * inv_h;              // exact binary fraction
    float sm = sinpif((float)m * a);
    float sd = sinpif(a);
    float s  = sm / (sd * (float)m);
    return make_float2(cospif(a) * s, -sm / (float)m);
}

// ---- upA r=2: transposed smem tile; row-pairs packed into f32x2 ----
template <int MM, int RS>
__device__ __forceinline__ void upA2_body(int blk, const float* __restrict__ x,
                                          float2* __restrict__ A, float* smraw) {
    const int HH = 2 * MM;
    const int RTOT = (256 / MM) * RS;         // 16
    float*  xs = smraw;                       // [MM][RTOT] (transposed)
    float2* ps = (float2*)(smraw + MM * RTOT);
    int tid = threadIdx.x;
    if (tid < MM) ps[tid] = phi_val(2 * tid + 1, MM, 1.f / (float)HH);
    int row0 = blk * RTOT;
    const float* xb = x + (size_t)row0 * MM;
#pragma unroll
    for (int i = tid; i < RTOT * MM; i += 256)
        xs[(i & (MM - 1)) * RTOT + (i / MM)] = xb[i];
    __syncthreads();
    int g = tid / MM, u = tid & (MM - 1);
    u64 arr[RS / 2], aii[RS / 2];
#pragma unroll
    for (int k = 0; k < RS / 2; ++k) { arr[k] = 0ull; aii[k] = 0ull; }
    const float* xg = xs + g * RS;
#pragma unroll 4
    for (int qy = 0; qy < MM; ++qy) {
        float2 p = ps[(u - qy) & (MM - 1)];
        u64 px2 = pack2(p.x, p.x), py2 = pack2(p.y, p.y);
        const float* col = xg + qy * RTOT;
#pragma unroll
        for (int rp = 0; rp < RS / 4; ++rp) {
            ulonglong2 vv = *(const ulonglong2*)(col + rp * 4);  // 4 rows
            fma2(arr[2 * rp],     vv.x, px2);
            fma2(arr[2 * rp + 1], vv.y, px2);
            fma2(aii[2 * rp],     vv.x, py2);
            fma2(aii[2 * rp + 1], vv.y, py2);
        }
    }
    float2* Ab = A + (size_t)row0 * HH;
#pragma unroll
    for (int k = 0; k < RS / 2; ++k) {
        float r0, r1, i0, i1;
        unpack2(arr[k], r0, r1);
        unpack2(aii[k], i0, i1);
        int rl = g * RS + 2 * k;
        Ab[(size_t)rl * HH + 2 * u + 1]       = make_float2(r0, i0);
        Ab[(size_t)(rl + 1) * HH + 2 * u + 1] = make_float2(r1, i1);
        Ab[(size_t)rl * HH + 2 * u]       = make_float2(xs[u * RTOT + rl], 0.f);
        Ab[(size_t)(rl + 1) * HH + 2 * u] = make_float2(xs[u * RTOT + rl + 1], 0.f);
    }
}

// ---- upA r=4 (combo 02): 8 rows/block; tids 192-255 write copies ----
__device__ __forceinline__ void upA4_body(int blk, const float* __restrict__ x,
                                          float2* __restrict__ A, float* smraw) {
    float*  xs = smraw;                       // [64][8] transposed
    float2* ps = (float2*)(smraw + 512);      // 192
    int tid = threadIdx.x;
    if (tid < 192)
        ps[tid] = phi_val(4 * (tid & 63) + (tid >> 6) + 1, 64, 1.f / 256.f);
    int row0 = blk * 8;
    const float* xb = x + (size_t)row0 * 64;
    for (int i = tid; i < 512; i += 256)
        xs[(i & 63) * 8 + (i >> 6)] = xb[i];
    __syncthreads();
    float2* Ab = A + (size_t)row0 * 256;
    if (tid < 192) {
        int cls = tid >> 6, u = tid & 63;
        const float2* pc = ps + cls * 64;
        u64 arr[4], aii[4];
#pragma unroll
        for (int k = 0; k < 4; ++k) { arr[k] = 0ull; aii[k] = 0ull; }
#pragma unroll 4
        for (int qy = 0; qy < 64; ++qy) {
            float2 p = pc[(u - qy) & 63];
            u64 px2 = pack2(p.x, p.x), py2 = pack2(p.y, p.y);
            const float* col = xs + qy * 8;
            ulonglong2 v0 = *(const ulonglong2*)(col);
            ulonglong2 v1 = *(const ulonglong2*)(col + 4);
            fma2(arr[0], v0.x, px2); fma2(arr[1], v0.y, px2);
            fma2(arr[2], v1.x, px2); fma2(arr[3], v1.y, px2);
            fma2(aii[0], v0.x, py2); fma2(aii[1], v0.y, py2);
            fma2(aii[2], v1.x, py2); fma2(aii[3], v1.y, py2);
        }
        int ty = 4 * u + cls + 1;
#pragma unroll
        for (int k = 0; k < 4; ++k) {
            float r0, r1, i0, i1;
            unpack2(arr[k], r0, r1);
            unpack2(aii[k], i0, i1);
            Ab[(size_t)(2 * k) * 256 + ty]     = make_float2(r0, i0);
            Ab[(size_t)(2 * k + 1) * 256 + ty] = make_float2(r1, i1);
        }
    } else {
        int u = tid - 192;
#pragma unroll
        for (int rr = 0; rr < 8; ++rr)
            Ab[(size_t)rr * 256 + 4 * u] = make_float2(xs[u * 8 + rr], 0.f);
    }
}

__global__ void __launch_bounds__(256) upA_kernel(const float* __restrict__ x1,
                                                  const float* __restrict__ x2) {
    extern __shared__ float smraw[];
    int bx = blockIdx.x;
    if (bx < 128)      upA2_body<128, 8>(bx, x1, g_A01, smraw);
    else if (bx < 256) upA4_body(bx - 128, x2, g_A02, smraw);
    else               upA2_body<64, 4>(bx - 256, x2, g_A12, smraw);
}

// ---- upB r=2: packed-complex accumulation, Re = lo - hi at the end ----
template <int MM, int TX>
__device__ __forceinline__ void upB2_core(int img, int t0, int ty,
                                          const float2* __restrict__ A,
                                          float* __restrict__ U,
                                          const float2* ps) {
    const int HH = 2 * MM;
    u64 acc2[TX];
#pragma unroll
    for (int i = 0; i < TX; ++i) acc2[i] = 0ull;
    const float2* Ab = A + (size_t)img * MM * HH + ty;
    float* Ub = U + (size_t)img * HH * HH;
#pragma unroll 2
    for (int qx = 0; qx < MM; ++qx) {
        float2 av = Ab[(size_t)qx * HH];
        if ((unsigned)(qx - t0) < (unsigned)TX)
            Ub[(size_t)(2 * qx) * HH + ty] = av.x;          // copy row
        u64 av2 = pack2(av.x, av.y);
        const u64* pp = (const u64*)(ps + ((t0 - qx) & (MM - 1)));
#pragma unroll
        for (int i = 0; i < TX; ++i) fma2(acc2[i], av2, pp[i]);
    }
#pragma unroll
    for (int i = 0; i < TX; ++i) {
        float lo, hi; unpack2(acc2[i], lo, hi);
        Ub[(size_t)(2 * (t0 + i) + 1) * HH + ty] = lo - hi;
    }
}

__device__ __forceinline__ void upB4_core(int img, int t0, int cls, int ty,
                                          const float2* __restrict__ A,
                                          float* __restrict__ U,
                                          const float2* ps) {
    u64 acc2[16];
#pragma unroll
    for (int i = 0; i < 16; ++i) acc2[i] = 0ull;
    const float2* Ab = A + (size_t)img * 64 * 256 + ty;
    float* Ub = U + (size_t)img * 256 * 256;
#pragma unroll 2
    for (int qx = 0; qx < 64; ++qx) {
        float2 av = Ab[(size_t)qx * 256];
        if (cls == 0 && (unsigned)(qx - t0) < 16u)
            Ub[(size_t)(4 * qx) * 256 + ty] = av.x;
        u64 av2 = pack2(av.x, av.y);
        const u64* pp = (const u64*)(ps + ((t0 - qx) & 63));
#pragma unroll
        for (int i = 0; i < 16; ++i) fma2(acc2[i], av2, pp[i]);
    }
#pragma unroll
    for (int i = 0; i < 16; ++i) {
        float lo, hi; unpack2(acc2[i], lo, hi);
        Ub[(size_t)(4 * (t0 + i) + cls + 1) * 256 + ty] = lo - hi;
    }
}

__global__ void __launch_bounds__(256) upB_kernel() {
    extern __shared__ float smraw[];
    float2* ps = (float2*)smraw;
    int bx = blockIdx.x, tid = threadIdx.x;
    if (bx < 128) {                            // upB01: MM=128, TX=16
        int img = bx >> 3, t0 = (bx & 7) * 16;
        if (tid < 128) { float2 v = phi_val(2 * tid + 1, 128, 1.f / 256.f); ps[tid] = v; ps[tid + 128] = v; }
        __syncthreads();
        upB2_core<128, 16>(img, t0, tid, g_A01, g_U01, ps);
        return;
    }
    bx -= 128;
    if (bx < 192) {                            // upB02: r=4
        int img = bx / 12, r = bx % 12, cls = r >> 2, t0 = (r & 3) * 16;
        if (tid < 64) { float2 v = phi_val(4 * tid + cls + 1, 64, 1.f / 256.f); ps[tid] = v; ps[tid + 64] = v; }
        __syncthreads();
        upB4_core(img, t0, cls, tid, g_A02, g_U02, ps);
        return;
    }
    bx -= 192;                                 // upB12: 2 images per block
    {
        int imgp = bx >> 2, t0 = (bx & 3) * 16;
        if (tid < 64) { float2 v = phi_val(2 * tid + 1, 64, 1.f / 128.f); ps[tid] = v; ps[tid + 64] = v; }
        __syncthreads();
        upB2_core<64, 16>(imgp * 2 + (tid >> 7), t0, tid & 127, g_A12, g_U12, ps);
    }
}

// ---- correlation: 128 threads, f32x2-packed 8x8 Gram accumulation ----
__device__ __forceinline__ void corr_body(const float* __restrict__ A,
                                          const float* __restrict__ B,
                                          float* __restrict__ out,
                                          int lm, int qblk, int s, int b,
                                          int sg, int trans, int pbase,
                                          float* smraw) {
    int h = 1 << lm, hh = h * h;
    int dx = sg * c_dx[s], dy = sg * c_dy[s];
    const float* Ab = A + (size_t)b * LCH * hh;
    const float* Bb = B + (size_t)b * LCH * hh;
    int q0 = qblk * 4096;
    u64 acc2[32];
#pragma unroll
    for (int k = 0; k < 32; ++k) acc2[k] = 0ull;
    for (int q = q0 + threadIdx.x; q < q0 + 4096; q += 128) {
        int qx = q >> lm;
        int qy = q & (h - 1);
        int fo = (((qx + dx) & (h - 1)) << lm) + ((qy + dy) & (h - 1));
        float a[8], c[8];
#pragma unroll
        for (int l = 0; l < 8; ++l) a[l] = Ab[(size_t)l * hh + fo];
#pragma unroll
        for (int l = 0; l < 8; ++l) c[l] = Bb[(size_t)l * hh + q];
        u64 c2[4], a2[8];
#pragma unroll
        for (int jj = 0; jj < 4; ++jj) c2[jj] = pack2(c[2 * jj], c[2 * jj + 1]);
#pragma unroll
        for (int i = 0; i < 8; ++i) a2[i] = pack2(a[i], a[i]);
#pragma unroll
        for (int i = 0; i < 8; ++i)
#pragma unroll
            for (int jj = 0; jj < 4; ++jj)
                fma2(acc2[i * 4 + jj], a2[i], c2[jj]);
    }
    u64* red = (u64*)smraw;                    // 32*4 u64
    int lane = threadIdx.x & 31;
    int wid  = threadIdx.x >> 5;
#pragma unroll
    for (int k = 0; k < 32; ++k) {
        u64 v = acc2[k];
        v = add2(v, __shfl_down_sync(0xffffffffu, v, 16));
        v = add2(v, __shfl_down_sync(0xffffffffu, v, 8));
        v = add2(v, __shfl_down_sync(0xffffffffu, v, 4));
        v = add2(v, __shfl_down_sync(0xffffffffu, v, 2));
        v = add2(v, __shfl_down_sync(0xffffffffu, v, 1));
        if (lane == 0) red[k * 4 + wid] = v;
    }
    __syncthreads();
    if (threadIdx.x < 32) {
        u64 sum = red[threadIdx.x * 4];
        sum = add2(sum, red[threadIdx.x * 4 + 1]);
        sum = add2(sum, red[threadIdx.x * 4 + 2]);
        sum = add2(sum, red[threadIdx.x * 4 + 3]);
        float lo, hi; unpack2(sum, lo, hi);
        int i = threadIdx.x >> 2, j0 = (threadIdx.x & 3) * 2;
        int p0 = trans ? (j0 * 8 + i) : (i * 8 + j0);
        int p1 = trans ? ((j0 + 1) * 8 + i) : (i * 8 + j0 + 1);
        atomicAdd(&out[(size_t)b * 2688 + (size_t)(pbase + p0) * 7 + s], lo);
        atomicAdd(&out[(size_t)b * 2688 + (size_t)(pbase + p1) * 7 + s], hi);
    }
}

__global__ void __launch_bounds__(128) corr_kernel(const float* __restrict__ x0,
                                                   const float* __restrict__ x1,
                                                   const float* __restrict__ x2,
                                                   float* __restrict__ out) {
    extern __shared__ float smraw[];
    int bx = blockIdx.x, s = blockIdx.y, b = blockIdx.z;
    if (bx < 16)      corr_body(x0,    x0, out, 8, bx,      s, b,  1, 0, 0,   smraw);
    else if (bx < 32) corr_body(g_U01, x0, out, 8, bx - 16, s, b, -1, 1, 64,  smraw);
    else if (bx < 48) corr_body(g_U02, x0, out, 8, bx - 32, s, b, -1, 1, 128, smraw);
    else if (bx < 52) corr_body(x1,    x1, out, 7, bx - 48, s, b,  1, 0, 192, smraw);
    else if (bx < 56) corr_body(g_U12, x1, out, 7, bx - 52, s, b, -1, 1, 256, smraw);
    else              corr_body(x2,    x2, out, 6, 0,       s, b,  1, 0, 320, smraw);
}

extern "C" void kernel_launch(void* const* d_in, const int* in_sizes, int n_in,
                              void* d_out, int out_size) {
    const float* x0 = nullptr;
    const float* x1 = nullptr;
    const float* x2 = nullptr;
    for (int i = 0; i < n_in; ++i) {
        if (in_sizes[i] == 2 * 8 * 256 * 256)      x0 = (const float*)d_in[i];
        else if (in_sizes[i] == 2 * 8 * 128 * 128) x1 = (const float*)d_in[i];
        else if (in_sizes[i] == 2 * 8 * 64 * 64)   x2 = (const float*)d_in[i];
    }
    float* out = (float*)d_out;

    cudaMemsetAsync(d_out, 0, (size_t)out_size * sizeof(float));
    upA_kernel<<<320, 256, 9216>>>(x1, x2);
    upB_kernel<<<352, 256, 2048>>>();
    corr_kernel<<<dim3(57, 7, 2), 128, 1024>>>(x0, x1, x2, out);
}